// round 3
// baseline (speedup 1.0000x reference)
#include <cuda_runtime.h>
#include <cstdint>
#include <cfloat>

// Problem constants (fixed by dataset)
#define NN    2048
#define TT    128
#define KSEL  20
#define MAXA  20
#define LRC   0.01f
#define EPSC  1e-8f
#define NW32  (NN/32)
#define QSPL  8            // i-range splits per step in k_main
#define ISEG  (NN/QSPL)    // 256

// ---------------- device scratch ---------------------------------------------
__device__ __align__(16) static float    g_ST[(size_t)NN * NN];   // sigma^T
__device__ static int16_t  g_act_idx[TT * MAXA];
__device__ static int      g_act_cnt[TT];
__device__ static int      g_act_cntfull[TT];
__device__ static unsigned g_act_mask[TT * NW32];
__device__ static float    g_part[(TT - 1) * QSPL * 2];
__device__ static int      g_done[TT - 1];

// ================= K_prep: transpose (blocks 0..4095) + top-K (4096..4223) ===
__global__ void __launch_bounds__(256)
k_prep(const int* __restrict__ tokens, const float* __restrict__ proj,
       const float* __restrict__ S) {
    const int bx  = blockIdx.x;
    const int tid = threadIdx.x;

    if (bx < (NN / 32) * (NN / 32)) {
        // -------- transpose 32x32 tile --------
        __shared__ float tile[32][33];
        const int tx = tid & 31, ty = tid >> 5;
        const int bi = bx & (NN / 32 - 1), bj = bx >> 6;
        const int x0 = bi * 32, y0 = bj * 32;
        int x = x0 + tx;
        #pragma unroll
        for (int r = 0; r < 32; r += 8)
            tile[ty + r][tx] = S[(size_t)(y0 + ty + r) * NN + x];
        __syncthreads();
        x = y0 + tx;
        #pragma unroll
        for (int r = 0; r < 32; r += 8)
            g_ST[(size_t)(x0 + ty + r) * NN + x] = tile[tx][ty + r];
        return;
    }

    // -------- top-K via 4-pass radix select (one block per token) --------
    const int t    = bx - (NN / 32) * (NN / 32);
    const int lane = tid & 31;
    const int base = tid * 8;

    __shared__ unsigned hist[256];
    __shared__ unsigned s_prefix;
    __shared__ int      s_kk;
    __shared__ unsigned s_mask[NW32];
    __shared__ int      s_cnt;

    const float* row = proj + (size_t)tokens[t] * NN;
    const float4* rv4 = reinterpret_cast<const float4*>(row + base);
    float4 a = rv4[0], b = rv4[1];
    float v[8] = {a.x, a.y, a.z, a.w, b.x, b.y, b.z, b.w};
    unsigned key[8];
    #pragma unroll
    for (int m = 0; m < 8; m++) {
        unsigned u = __float_as_uint(v[m]);
        key[m] = (u >> 31) ? ~u : (u | 0x80000000u);
    }

    if (tid == 0) { s_prefix = 0u; s_kk = KSEL; }
    unsigned prefix = 0u;
    int kk = KSEL;

    #pragma unroll
    for (int bp = 3; bp >= 0; bp--) {
        hist[tid] = 0u;
        __syncthreads();
        #pragma unroll
        for (int m = 0; m < 8; m++) {
            bool match = (bp == 3) || ((key[m] >> ((bp + 1) * 8)) == prefix);
            if (match) atomicAdd(&hist[(key[m] >> (bp * 8)) & 0xFFu], 1u);
        }
        __syncthreads();
        if (tid < 32) {
            const int top = 255 - lane * 8;
            unsigned local = 0;
            unsigned hv[8];
            #pragma unroll
            for (int q = 0; q < 8; q++) { hv[q] = hist[top - q]; local += hv[q]; }
            unsigned incl = local;
            #pragma unroll
            for (int o = 1; o < 32; o <<= 1) {
                unsigned u = __shfl_up_sync(0xFFFFFFFFu, incl, o);
                if (lane >= o) incl += u;
            }
            unsigned excl = incl - local;
            if (excl < (unsigned)kk && incl >= (unsigned)kk) {
                unsigned e = excl;
                #pragma unroll
                for (int q = 0; q < 8; q++) {
                    if (e + hv[q] >= (unsigned)kk) {
                        s_prefix = (prefix << 8) | (unsigned)(top - q);
                        s_kk = kk - (int)e;
                        break;
                    }
                    e += hv[q];
                }
            }
        }
        __syncthreads();
        prefix = s_prefix;
        kk = s_kk;
    }
    const unsigned key_thr = prefix;

    if (tid < NW32) s_mask[tid] = 0u;
    if (tid == 0)   s_cnt = 0;
    __syncthreads();

    #pragma unroll
    for (int m = 0; m < 8; m++) {
        if (key[m] >= key_thr) {
            int i = base + m;
            atomicOr(&s_mask[i >> 5], 1u << (i & 31));
            int p = atomicAdd(&s_cnt, 1);
            if (p < MAXA) g_act_idx[t * MAXA + p] = (int16_t)i;
        }
    }
    __syncthreads();

    // pad unused idx slots with 0 so k_main can fully unroll with safe loads
    const int cc = (s_cnt < MAXA) ? s_cnt : MAXA;
    if (tid >= cc && tid < MAXA) g_act_idx[t * MAXA + tid] = 0;

    if (tid < NW32) g_act_mask[t * NW32 + tid] = s_mask[tid];
    if (tid == 0) {
        g_act_cntfull[t] = s_cnt;
        g_act_cnt[t]     = cc;
        if (t < TT - 1) g_done[t] = 0;
    }
}

// ================= K_main: QSPL CTAs per step t ===============================
__global__ void __launch_bounds__(128)
k_main(const int* __restrict__ plast, float* __restrict__ out) {
    const int bx   = blockIdx.x;
    const int t    = bx >> 3;          // 0..126
    const int q    = bx & (QSPL - 1);
    const int lo   = q * ISEG;
    const int tid  = threadIdx.x;      // 128
    const int lane = tid & 31;
    const int w    = tid >> 5;
    const int i0   = lo + tid * 2;

    __shared__ unsigned s_cntw[MAXA * ISEG / 4];   // 5120 B packed byte counts
    __shared__ int16_t  s_idx[TT * MAXA];          // 5120 B
    __shared__ uint8_t  s_acnt[TT];
    __shared__ uint8_t  s_pos[NN];                 // j -> js (0xFF = not in A(t))
    __shared__ float    s_red[8];

    const int plasticity = *plast;

    for (int x = tid; x < TT * MAXA / 2; x += 128)
        reinterpret_cast<int*>(s_idx)[x] = reinterpret_cast<const int*>(g_act_idx)[x];
    for (int x = tid; x < TT; x += 128) s_acnt[x] = (uint8_t)g_act_cnt[x];
    for (int x = tid; x < NN / 4; x += 128)
        reinterpret_cast<unsigned*>(s_pos)[x] = 0xFFFFFFFFu;
    if (plasticity)
        for (int x = tid; x < MAXA * ISEG / 4; x += 128) s_cntw[x] = 0u;
    __syncthreads();

    const int cnt_t = s_acnt[t];
    if (tid < cnt_t) s_pos[(int)s_idx[t * MAXA + tid]] = (uint8_t)tid;
    __syncthreads();

    // phase 1: base pred — fully unrolled, 20 independent LDG.64s in flight
    float p0 = 0.f, p1 = 0.f;
    int   jreg[MAXA];
    #pragma unroll
    for (int js = 0; js < MAXA; js++)
        jreg[js] = s_idx[t * MAXA + js];
    #pragma unroll
    for (int js = 0; js < MAXA; js++) {
        const float2 r =
            *reinterpret_cast<const float2*>(g_ST + (size_t)jreg[js] * NN + i0);
        if (js < cnt_t) { p0 += r.x; p1 += r.y; }
    }

    if (plasticity) {
        // phase 2: counts c_t(i,j) via direct scan of s < t (pad-32 layout, no div)
        for (int wk = tid; wk < t * 32; wk += 128) {
            const int s = wk >> 5;
            const int m = wk & 31;
            if (m < s_acnt[s]) {
                const int j  = s_idx[s * MAXA + m];
                const int js = s_pos[j];
                if (js != 0xFF) {
                    const int c2 = s_acnt[s + 1];
                    const int b2 = (s + 1) * MAXA;
                    for (int mm = 0; mm < c2; mm++) {
                        const int i = s_idx[b2 + mm];
                        const unsigned d = (unsigned)(i - lo);
                        if (d < (unsigned)ISEG) {
                            const unsigned off = (unsigned)js * ISEG + d;
                            atomicAdd(&s_cntw[off >> 2], 1u << ((off & 3u) * 8u));
                        }
                    }
                }
            }
        }
        __syncthreads();

        // phase 3: sparse clip corrections; reload from g_ST (same lines as
        // phase 1 -> L1 hits), executed only on the rare nonzero-count path
        const unsigned sh = (tid & 1) * 16;
        #pragma unroll
        for (int js = 0; js < MAXA; js++) {
            const unsigned word = s_cntw[(unsigned)js * (ISEG / 4) + (tid >> 1)];
            const unsigned two  = (word >> sh) & 0xFFFFu;
            if (two) {
                const float2 r =
                    *reinterpret_cast<const float2*>(g_ST + (size_t)jreg[js] * NN + i0);
                const unsigned c0 = two & 0xFFu, c1 = (two >> 8) & 0xFFu;
                if (c0) p0 += fminf(r.x + LRC * (float)c0, 1.0f) - r.x;
                if (c1) p1 += fminf(r.y + LRC * (float)c1, 1.0f) - r.y;
            }
        }
    }

    // reduction over segment
    const unsigned mword = g_act_mask[(t + 1) * NW32 + (i0 >> 5)];
    float pn2 = p0 * p0 + p1 * p1;
    float dt  = 0.f;
    if ((mword >> (i0 & 31)) & 1u)       dt += p0;
    if ((mword >> ((i0 + 1) & 31)) & 1u) dt += p1;
    #pragma unroll
    for (int o = 16; o; o >>= 1) {
        pn2 += __shfl_xor_sync(0xFFFFFFFFu, pn2, o);
        dt  += __shfl_xor_sync(0xFFFFFFFFu, dt, o);
    }
    if (lane == 0) { s_red[2 * w] = pn2; s_red[2 * w + 1] = dt; }
    __syncthreads();

    if (tid == 0) {
        float P2 = 0.f, D = 0.f;
        #pragma unroll
        for (int r = 0; r < 4; r++) { P2 += s_red[2 * r]; D += s_red[2 * r + 1]; }
        g_part[(t * QSPL + q) * 2 + 0] = P2;
        g_part[(t * QSPL + q) * 2 + 1] = D;
        __threadfence();
        const int d = atomicAdd(&g_done[t], 1);
        if (d == QSPL - 1) {
            __threadfence();
            float TP2 = 0.f, TD = 0.f;
            #pragma unroll
            for (int s = 0; s < QSPL; s++) {
                TP2 += g_part[(t * QSPL + s) * 2 + 0];
                TD  += g_part[(t * QSPL + s) * 2 + 1];
            }
            const float pn = sqrtf(TP2);
            float tension;
            if (plasticity) {
                const float overlap = TD / (pn * sqrtf((float)KSEL) + EPSC);
                tension = (pn > 0.0f) ? (1.0f - overlap) : 1.0f;
            } else {
                const float xn = sqrtf((float)g_act_cntfull[t + 1]);
                tension = 1.0f - TD / (pn * xn + EPSC);
            }
            out[t] = tension;
        }
    }
}

// ---------------- launch ------------------------------------------------------
extern "C" void kernel_launch(void* const* d_in, const int* in_sizes, int n_in,
                              void* d_out, int out_size) {
    const int*   tokens = (const int*)d_in[0];
    const float* proj   = (const float*)d_in[1];
    const float* sigma  = (const float*)d_in[2];
    const int*   plast  = (const int*)d_in[3];
    float*       out    = (float*)d_out;

    k_prep<<<(NN / 32) * (NN / 32) + TT, 256>>>(tokens, proj, sigma);
    k_main<<<(TT - 1) * QSPL, 128>>>(plast, out);
}

// round 4
// speedup vs baseline: 1.2141x; 1.2141x over previous
#include <cuda_runtime.h>
#include <cstdint>
#include <cfloat>

// Problem constants (fixed by dataset)
#define NN    2048
#define TT    128
#define KSEL  20
#define MAXA  20
#define LRC   0.01f
#define EPSC  1e-8f
#define NW32  (NN/32)
#define QSPL  8            // i-range splits per step in k_main
#define ISEG  (NN/QSPL)    // 256
#define MCAP  2560         // >= worst-case matches per t (126*20)

// ---------------- device scratch ---------------------------------------------
__device__ __align__(16) static float    g_ST[(size_t)NN * NN];   // sigma^T
__device__ static int16_t  g_act_idx[TT * MAXA];
__device__ static int      g_act_cnt[TT];
__device__ static int      g_act_cntfull[TT];
__device__ static unsigned g_act_mask[TT * NW32];
__device__ static unsigned g_match[(TT - 1) * MCAP];   // (js | s1<<8 | c2<<16)
__device__ static int      g_match_cnt[TT - 1];
__device__ static float    g_part[(TT - 1) * QSPL * 2];
__device__ static int      g_done[TT - 1];

// ================= K_prep: transpose (blocks 0..4095) + top-K (4096..4223) ===
__global__ void __launch_bounds__(256)
k_prep(const int* __restrict__ tokens, const float* __restrict__ proj,
       const float* __restrict__ S) {
    const int bx  = blockIdx.x;
    const int tid = threadIdx.x;

    if (bx < (NN / 32) * (NN / 32)) {
        __shared__ float tile[32][33];
        const int tx = tid & 31, ty = tid >> 5;
        const int bi = bx & (NN / 32 - 1), bj = bx >> 6;
        const int x0 = bi * 32, y0 = bj * 32;
        int x = x0 + tx;
        #pragma unroll
        for (int r = 0; r < 32; r += 8)
            tile[ty + r][tx] = S[(size_t)(y0 + ty + r) * NN + x];
        __syncthreads();
        x = y0 + tx;
        #pragma unroll
        for (int r = 0; r < 32; r += 8)
            g_ST[(size_t)(x0 + ty + r) * NN + x] = tile[tx][ty + r];
        return;
    }

    // -------- top-K via 4-pass radix select (one block per token) --------
    const int t    = bx - (NN / 32) * (NN / 32);
    const int lane = tid & 31;
    const int base = tid * 8;

    __shared__ unsigned hist[256];
    __shared__ unsigned s_prefix;
    __shared__ int      s_kk;
    __shared__ unsigned s_mask[NW32];
    __shared__ int      s_cnt;

    const float* row = proj + (size_t)tokens[t] * NN;
    const float4* rv4 = reinterpret_cast<const float4*>(row + base);
    float4 a = rv4[0], b = rv4[1];
    float v[8] = {a.x, a.y, a.z, a.w, b.x, b.y, b.z, b.w};
    unsigned key[8];
    #pragma unroll
    for (int m = 0; m < 8; m++) {
        unsigned u = __float_as_uint(v[m]);
        key[m] = (u >> 31) ? ~u : (u | 0x80000000u);
    }

    if (tid == 0) { s_prefix = 0u; s_kk = KSEL; }
    unsigned prefix = 0u;
    int kk = KSEL;

    #pragma unroll
    for (int bp = 3; bp >= 0; bp--) {
        hist[tid] = 0u;
        __syncthreads();
        #pragma unroll
        for (int m = 0; m < 8; m++) {
            bool match = (bp == 3) || ((key[m] >> ((bp + 1) * 8)) == prefix);
            if (match) atomicAdd(&hist[(key[m] >> (bp * 8)) & 0xFFu], 1u);
        }
        __syncthreads();
        if (tid < 32) {
            const int top = 255 - lane * 8;
            unsigned local = 0;
            unsigned hv[8];
            #pragma unroll
            for (int q = 0; q < 8; q++) { hv[q] = hist[top - q]; local += hv[q]; }
            unsigned incl = local;
            #pragma unroll
            for (int o = 1; o < 32; o <<= 1) {
                unsigned u = __shfl_up_sync(0xFFFFFFFFu, incl, o);
                if (lane >= o) incl += u;
            }
            unsigned excl = incl - local;
            if (excl < (unsigned)kk && incl >= (unsigned)kk) {
                unsigned e = excl;
                #pragma unroll
                for (int q = 0; q < 8; q++) {
                    if (e + hv[q] >= (unsigned)kk) {
                        s_prefix = (prefix << 8) | (unsigned)(top - q);
                        s_kk = kk - (int)e;
                        break;
                    }
                    e += hv[q];
                }
            }
        }
        __syncthreads();
        prefix = s_prefix;
        kk = s_kk;
    }
    const unsigned key_thr = prefix;

    if (tid < NW32) s_mask[tid] = 0u;
    if (tid == 0)   s_cnt = 0;
    __syncthreads();

    #pragma unroll
    for (int m = 0; m < 8; m++) {
        if (key[m] >= key_thr) {
            int i = base + m;
            atomicOr(&s_mask[i >> 5], 1u << (i & 31));
            int p = atomicAdd(&s_cnt, 1);
            if (p < MAXA) g_act_idx[t * MAXA + p] = (int16_t)i;
        }
    }
    __syncthreads();

    const int cc = (s_cnt < MAXA) ? s_cnt : MAXA;
    if (tid >= cc && tid < MAXA) g_act_idx[t * MAXA + tid] = 0;

    if (tid < NW32) g_act_mask[t * NW32 + tid] = s_mask[tid];
    if (tid == 0) {
        g_act_cntfull[t] = s_cnt;
        g_act_cnt[t]     = cc;
        if (t < TT - 1) g_done[t] = 0;
    }
}

// ================= K_match: per-t match list (scan done ONCE) ================
__global__ void __launch_bounds__(128)
k_match(const int* __restrict__ plast) {
    const int t   = blockIdx.x;        // 0..126
    const int tid = threadIdx.x;

    __shared__ int16_t s_idx[TT * MAXA];   // 5120 B
    __shared__ uint8_t s_acnt[TT];
    __shared__ uint8_t s_pos[NN];
    __shared__ int     s_cnt;

    if (!*plast) { if (tid == 0) g_match_cnt[t] = 0; return; }

    for (int x = tid; x < TT * MAXA / 2; x += 128)
        reinterpret_cast<int*>(s_idx)[x] = reinterpret_cast<const int*>(g_act_idx)[x];
    for (int x = tid; x < TT; x += 128) s_acnt[x] = (uint8_t)g_act_cnt[x];
    for (int x = tid; x < NN / 4; x += 128)
        reinterpret_cast<unsigned*>(s_pos)[x] = 0xFFFFFFFFu;
    if (tid == 0) s_cnt = 0;
    __syncthreads();

    const int cnt_t = s_acnt[t];
    if (tid < cnt_t) s_pos[(int)s_idx[t * MAXA + tid]] = (uint8_t)tid;
    __syncthreads();

    for (int wk = tid; wk < t * 32; wk += 128) {
        const int s = wk >> 5;
        const int m = wk & 31;
        if (m < s_acnt[s]) {
            const int j  = s_idx[s * MAXA + m];
            const int js = s_pos[j];
            if (js != 0xFF) {
                const int pos = atomicAdd(&s_cnt, 1);
                g_match[t * MCAP + pos] =
                    (unsigned)js | ((unsigned)(s + 1) << 8) |
                    ((unsigned)s_acnt[s + 1] << 16);
            }
        }
    }
    __syncthreads();
    if (tid == 0) g_match_cnt[t] = s_cnt;
}

// ================= K_main: QSPL CTAs per step t ===============================
__global__ void __launch_bounds__(128)
k_main(const int* __restrict__ plast, float* __restrict__ out) {
    const int bx   = blockIdx.x;
    const int t    = bx >> 3;          // 0..126
    const int q    = bx & (QSPL - 1);
    const int lo   = q * ISEG;
    const int tid  = threadIdx.x;      // 128
    const int lane = tid & 31;
    const int w    = tid >> 5;
    const int i0   = lo + tid * 2;

    __shared__ unsigned s_cntw[MAXA * ISEG / 4];   // 5120 B packed byte counts
    __shared__ float    s_red[8];

    const int plasticity = *plast;

    if (plasticity)
        for (int x = tid; x < MAXA * ISEG / 4; x += 128) s_cntw[x] = 0u;

    // phase 1: base pred — fully unrolled, 20 independent LDG.64s in flight
    const int cnt_t = g_act_cnt[t];
    int jreg[MAXA];
    #pragma unroll
    for (int js = 0; js < MAXA; js++)
        jreg[js] = (int)g_act_idx[t * MAXA + js];
    float p0 = 0.f, p1 = 0.f;
    #pragma unroll
    for (int js = 0; js < MAXA; js++) {
        const float2 r =
            *reinterpret_cast<const float2*>(g_ST + (size_t)jreg[js] * NN + i0);
        if (js < cnt_t) { p0 += r.x; p1 += r.y; }
    }

    if (plasticity) {
        __syncthreads();   // counters zeroed before atomics

        // phase 2: apply precomputed match list (~25 entries expected)
        const int nm = g_match_cnt[t];
        for (int e = tid; e < nm; e += 128) {
            const unsigned ent = g_match[t * MCAP + e];
            const int js = (int)(ent & 0xFFu);
            const int b2 = (int)((ent >> 8) & 0xFFu) * MAXA;
            const int c2 = (int)(ent >> 16);
            for (int mm = 0; mm < c2; mm++) {
                const int i = (int)g_act_idx[b2 + mm];
                const unsigned d = (unsigned)(i - lo);
                if (d < (unsigned)ISEG)
                    atomicAdd(&s_cntw[((unsigned)js * ISEG + d) >> 2],
                              1u << ((d & 3u) * 8u));
            }
        }
        __syncthreads();

        // phase 3: sparse clip corrections (g_ST reload -> L1 hits)
        const unsigned sh = (tid & 1) * 16;
        #pragma unroll
        for (int js = 0; js < MAXA; js++) {
            const unsigned word = s_cntw[(unsigned)js * (ISEG / 4) + (tid >> 1)];
            const unsigned two  = (word >> sh) & 0xFFFFu;
            if (two) {
                const float2 r =
                    *reinterpret_cast<const float2*>(g_ST + (size_t)jreg[js] * NN + i0);
                const unsigned c0 = two & 0xFFu, c1 = (two >> 8) & 0xFFu;
                if (c0) p0 += fminf(r.x + LRC * (float)c0, 1.0f) - r.x;
                if (c1) p1 += fminf(r.y + LRC * (float)c1, 1.0f) - r.y;
            }
        }
    }

    // reduction over segment
    const unsigned mword = g_act_mask[(t + 1) * NW32 + (i0 >> 5)];
    float pn2 = p0 * p0 + p1 * p1;
    float dt  = 0.f;
    if ((mword >> (i0 & 31)) & 1u)       dt += p0;
    if ((mword >> ((i0 + 1) & 31)) & 1u) dt += p1;
    #pragma unroll
    for (int o = 16; o; o >>= 1) {
        pn2 += __shfl_xor_sync(0xFFFFFFFFu, pn2, o);
        dt  += __shfl_xor_sync(0xFFFFFFFFu, dt, o);
    }
    if (lane == 0) { s_red[2 * w] = pn2; s_red[2 * w + 1] = dt; }
    __syncthreads();

    if (tid == 0) {
        float P2 = 0.f, D = 0.f;
        #pragma unroll
        for (int r = 0; r < 4; r++) { P2 += s_red[2 * r]; D += s_red[2 * r + 1]; }
        g_part[(t * QSPL + q) * 2 + 0] = P2;
        g_part[(t * QSPL + q) * 2 + 1] = D;
        __threadfence();
        const int d = atomicAdd(&g_done[t], 1);
        if (d == QSPL - 1) {
            __threadfence();
            float TP2 = 0.f, TD = 0.f;
            #pragma unroll
            for (int s = 0; s < QSPL; s++) {
                TP2 += g_part[(t * QSPL + s) * 2 + 0];
                TD  += g_part[(t * QSPL + s) * 2 + 1];
            }
            const float pn = sqrtf(TP2);
            float tension;
            if (plasticity) {
                const float overlap = TD / (pn * sqrtf((float)KSEL) + EPSC);
                tension = (pn > 0.0f) ? (1.0f - overlap) : 1.0f;
            } else {
                const float xn = sqrtf((float)g_act_cntfull[t + 1]);
                tension = 1.0f - TD / (pn * xn + EPSC);
            }
            out[t] = tension;
        }
    }
}

// ---------------- launch ------------------------------------------------------
extern "C" void kernel_launch(void* const* d_in, const int* in_sizes, int n_in,
                              void* d_out, int out_size) {
    const int*   tokens = (const int*)d_in[0];
    const float* proj   = (const float*)d_in[1];
    const float* sigma  = (const float*)d_in[2];
    const int*   plast  = (const int*)d_in[3];
    float*       out    = (float*)d_out;

    k_prep<<<(NN / 32) * (NN / 32) + TT, 256>>>(tokens, proj, sigma);
    k_match<<<TT - 1, 128>>>(plast);
    k_main<<<(TT - 1) * QSPL, 128>>>(plast, out);
}

// round 5
// speedup vs baseline: 1.2248x; 1.0088x over previous
#include <cuda_runtime.h>
#include <cstdint>
#include <cfloat>

// Problem constants (fixed by dataset)
#define NN    2048
#define TT    128
#define KSEL  20
#define MAXA  20
#define LRC   0.01f
#define EPSC  1e-8f
#define NW32  (NN/32)
#define QSPL  8            // i-range splits per step in k_main
#define ISEG  (NN/QSPL)    // 256
#define MCAP  2560         // >= worst-case matches per t
#define NTB   (NN/64)      // 32 transpose tiles per dim
#define NTRB  (NTB*NTB)    // 1024 transpose blocks

// ---------------- device scratch ---------------------------------------------
__device__ __align__(16) static float    g_ST[(size_t)NN * NN];   // sigma^T
__device__ static int16_t  g_act_idx[TT * MAXA];
__device__ static int      g_act_cnt[TT];
__device__ static int      g_act_cntfull[TT];
__device__ static unsigned g_act_mask[TT * NW32];
__device__ static unsigned g_match[(TT - 1) * MCAP];   // (js | s1<<8 | c2<<16)
__device__ static int      g_match_cnt[TT - 1];
__device__ static float    g_part[(TT - 1) * QSPL * 2];
__device__ static int      g_done[TT - 1];

// ======== K_prep: 64x64 float4 transpose (blocks 0..1023) + top-K ============
__global__ void __launch_bounds__(256)
k_prep(const int* __restrict__ tokens, const float* __restrict__ proj,
       const float* __restrict__ S) {
    const int bx  = blockIdx.x;
    const int tid = threadIdx.x;

    if (bx < NTRB) {
        // -------- 64x64 tile transpose, 128-bit both directions --------
        __shared__ float tile[64][65];
        const int tx = tid & 15;           // float4 column
        const int ty = tid >> 4;           // 0..15
        const int bi = bx & (NTB - 1), bj = bx >> 5;
        const int x0 = bi * 64, y0 = bj * 64;

        #pragma unroll
        for (int r = 0; r < 4; r++) {
            const int row = ty + 16 * r;
            const float4 v = *reinterpret_cast<const float4*>(
                S + (size_t)(y0 + row) * NN + x0 + 4 * tx);
            tile[row][4 * tx + 0] = v.x;
            tile[row][4 * tx + 1] = v.y;
            tile[row][4 * tx + 2] = v.z;
            tile[row][4 * tx + 3] = v.w;
        }
        __syncthreads();
        #pragma unroll
        for (int r = 0; r < 4; r++) {
            const int row = ty + 16 * r;
            float4 w;
            w.x = tile[4 * tx + 0][row];
            w.y = tile[4 * tx + 1][row];
            w.z = tile[4 * tx + 2][row];
            w.w = tile[4 * tx + 3][row];
            *reinterpret_cast<float4*>(
                g_ST + (size_t)(x0 + row) * NN + y0 + 4 * tx) = w;
        }
        return;
    }

    // -------- top-K via 4-pass radix select (one block per token) --------
    const int t    = bx - NTRB;
    const int lane = tid & 31;
    const int base = tid * 8;

    __shared__ unsigned hist[256];
    __shared__ unsigned s_prefix;
    __shared__ int      s_kk;
    __shared__ unsigned s_mask[NW32];
    __shared__ int      s_cnt;

    const float* row = proj + (size_t)tokens[t] * NN;
    const float4* rv4 = reinterpret_cast<const float4*>(row + base);
    float4 a = rv4[0], b = rv4[1];
    float v[8] = {a.x, a.y, a.z, a.w, b.x, b.y, b.z, b.w};
    unsigned key[8];
    #pragma unroll
    for (int m = 0; m < 8; m++) {
        unsigned u = __float_as_uint(v[m]);
        key[m] = (u >> 31) ? ~u : (u | 0x80000000u);
    }

    if (tid == 0) { s_prefix = 0u; s_kk = KSEL; }
    unsigned prefix = 0u;
    int kk = KSEL;

    #pragma unroll
    for (int bp = 3; bp >= 0; bp--) {
        hist[tid] = 0u;
        __syncthreads();
        #pragma unroll
        for (int m = 0; m < 8; m++) {
            bool match = (bp == 3) || ((key[m] >> ((bp + 1) * 8)) == prefix);
            if (match) atomicAdd(&hist[(key[m] >> (bp * 8)) & 0xFFu], 1u);
        }
        __syncthreads();
        if (tid < 32) {
            const int top = 255 - lane * 8;
            unsigned local = 0;
            unsigned hv[8];
            #pragma unroll
            for (int q = 0; q < 8; q++) { hv[q] = hist[top - q]; local += hv[q]; }
            unsigned incl = local;
            #pragma unroll
            for (int o = 1; o < 32; o <<= 1) {
                unsigned u = __shfl_up_sync(0xFFFFFFFFu, incl, o);
                if (lane >= o) incl += u;
            }
            unsigned excl = incl - local;
            if (excl < (unsigned)kk && incl >= (unsigned)kk) {
                unsigned e = excl;
                #pragma unroll
                for (int q = 0; q < 8; q++) {
                    if (e + hv[q] >= (unsigned)kk) {
                        s_prefix = (prefix << 8) | (unsigned)(top - q);
                        s_kk = kk - (int)e;
                        break;
                    }
                    e += hv[q];
                }
            }
        }
        __syncthreads();
        prefix = s_prefix;
        kk = s_kk;
    }
    const unsigned key_thr = prefix;

    if (tid < NW32) s_mask[tid] = 0u;
    if (tid == 0)   s_cnt = 0;
    __syncthreads();

    #pragma unroll
    for (int m = 0; m < 8; m++) {
        if (key[m] >= key_thr) {
            int i = base + m;
            atomicOr(&s_mask[i >> 5], 1u << (i & 31));
            int p = atomicAdd(&s_cnt, 1);
            if (p < MAXA) g_act_idx[t * MAXA + p] = (int16_t)i;
        }
    }
    __syncthreads();

    const int cc = (s_cnt < MAXA) ? s_cnt : MAXA;
    if (tid >= cc && tid < MAXA) g_act_idx[t * MAXA + tid] = 0;

    if (tid < NW32) g_act_mask[t * NW32 + tid] = s_mask[tid];
    if (tid == 0) {
        g_act_cntfull[t] = s_cnt;
        g_act_cnt[t]     = cc;
        if (t < TT - 1) g_done[t] = 0;
    }
}

// ================= K_match: per-t match list (scan done ONCE) ================
__global__ void __launch_bounds__(128)
k_match(const int* __restrict__ plast) {
    const int t   = blockIdx.x;        // 0..126
    const int tid = threadIdx.x;

    __shared__ int16_t s_idx[TT * MAXA];
    __shared__ uint8_t s_acnt[TT];
    __shared__ uint8_t s_pos[NN];
    __shared__ int     s_cnt;

    if (!*plast) { if (tid == 0) g_match_cnt[t] = 0; return; }

    for (int x = tid; x < TT * MAXA / 2; x += 128)
        reinterpret_cast<int*>(s_idx)[x] = reinterpret_cast<const int*>(g_act_idx)[x];
    for (int x = tid; x < TT; x += 128) s_acnt[x] = (uint8_t)g_act_cnt[x];
    for (int x = tid; x < NN / 4; x += 128)
        reinterpret_cast<unsigned*>(s_pos)[x] = 0xFFFFFFFFu;
    if (tid == 0) s_cnt = 0;
    __syncthreads();

    const int cnt_t = s_acnt[t];
    if (tid < cnt_t) s_pos[(int)s_idx[t * MAXA + tid]] = (uint8_t)tid;
    __syncthreads();

    for (int wk = tid; wk < t * 32; wk += 128) {
        const int s = wk >> 5;
        const int m = wk & 31;
        if (m < s_acnt[s]) {
            const int j  = s_idx[s * MAXA + m];
            const int js = s_pos[j];
            if (js != 0xFF) {
                const int pos = atomicAdd(&s_cnt, 1);
                g_match[t * MCAP + pos] =
                    (unsigned)js | ((unsigned)(s + 1) << 8) |
                    ((unsigned)s_acnt[s + 1] << 16);
            }
        }
    }
    __syncthreads();
    if (tid == 0) g_match_cnt[t] = s_cnt;
}

// ================= K_main: QSPL CTAs per step t ===============================
__global__ void __launch_bounds__(128)
k_main(const int* __restrict__ plast, float* __restrict__ out) {
    const int bx   = blockIdx.x;
    const int t    = bx >> 3;          // 0..126
    const int q    = bx & (QSPL - 1);
    const int lo   = q * ISEG;
    const int tid  = threadIdx.x;      // 128
    const int lane = tid & 31;
    const int w    = tid >> 5;
    const int i0   = lo + tid * 2;

    __shared__ unsigned s_cntw[MAXA * ISEG / 4];   // 5120 B packed byte counts
    __shared__ float    s_red[8];

    const int plasticity = *plast;

    if (plasticity)
        for (int x = tid; x < MAXA * ISEG / 4; x += 128) s_cntw[x] = 0u;

    // phase 1: base pred — fully unrolled, 20 independent LDG.64s in flight
    const int cnt_t = g_act_cnt[t];
    int jreg[MAXA];
    #pragma unroll
    for (int js = 0; js < MAXA; js++)
        jreg[js] = (int)g_act_idx[t * MAXA + js];
    float p0 = 0.f, p1 = 0.f;
    #pragma unroll
    for (int js = 0; js < MAXA; js++) {
        const float2 r =
            *reinterpret_cast<const float2*>(g_ST + (size_t)jreg[js] * NN + i0);
        if (js < cnt_t) { p0 += r.x; p1 += r.y; }
    }

    if (plasticity) {
        __syncthreads();   // counters zeroed before atomics

        // phase 2: apply precomputed match list (~25 entries expected)
        const int nm = g_match_cnt[t];
        for (int e = tid; e < nm; e += 128) {
            const unsigned ent = g_match[t * MCAP + e];
            const int js = (int)(ent & 0xFFu);
            const int b2 = (int)((ent >> 8) & 0xFFu) * MAXA;
            const int c2 = (int)(ent >> 16);
            for (int mm = 0; mm < c2; mm++) {
                const int i = (int)g_act_idx[b2 + mm];
                const unsigned d = (unsigned)(i - lo);
                if (d < (unsigned)ISEG)
                    atomicAdd(&s_cntw[((unsigned)js * ISEG + d) >> 2],
                              1u << ((d & 3u) * 8u));
            }
        }
        __syncthreads();

        // phase 3: sparse clip corrections (g_ST reload -> L1 hits)
        const unsigned sh = (tid & 1) * 16;
        #pragma unroll
        for (int js = 0; js < MAXA; js++) {
            const unsigned word = s_cntw[(unsigned)js * (ISEG / 4) + (tid >> 1)];
            const unsigned two  = (word >> sh) & 0xFFFFu;
            if (two) {
                const float2 r =
                    *reinterpret_cast<const float2*>(g_ST + (size_t)jreg[js] * NN + i0);
                const unsigned c0 = two & 0xFFu, c1 = (two >> 8) & 0xFFu;
                if (c0) p0 += fminf(r.x + LRC * (float)c0, 1.0f) - r.x;
                if (c1) p1 += fminf(r.y + LRC * (float)c1, 1.0f) - r.y;
            }
        }
    }

    // reduction over segment
    const unsigned mword = g_act_mask[(t + 1) * NW32 + (i0 >> 5)];
    float pn2 = p0 * p0 + p1 * p1;
    float dt  = 0.f;
    if ((mword >> (i0 & 31)) & 1u)       dt += p0;
    if ((mword >> ((i0 + 1) & 31)) & 1u) dt += p1;
    #pragma unroll
    for (int o = 16; o; o >>= 1) {
        pn2 += __shfl_xor_sync(0xFFFFFFFFu, pn2, o);
        dt  += __shfl_xor_sync(0xFFFFFFFFu, dt, o);
    }
    if (lane == 0) { s_red[2 * w] = pn2; s_red[2 * w + 1] = dt; }
    __syncthreads();

    if (tid == 0) {
        float P2 = 0.f, D = 0.f;
        #pragma unroll
        for (int r = 0; r < 4; r++) { P2 += s_red[2 * r]; D += s_red[2 * r + 1]; }
        g_part[(t * QSPL + q) * 2 + 0] = P2;
        g_part[(t * QSPL + q) * 2 + 1] = D;
        __threadfence();
        const int d = atomicAdd(&g_done[t], 1);
        if (d == QSPL - 1) {
            __threadfence();
            float TP2 = 0.f, TD = 0.f;
            #pragma unroll
            for (int s = 0; s < QSPL; s++) {
                TP2 += g_part[(t * QSPL + s) * 2 + 0];
                TD  += g_part[(t * QSPL + s) * 2 + 1];
            }
            const float pn = sqrtf(TP2);
            float tension;
            if (plasticity) {
                const float overlap = TD / (pn * sqrtf((float)KSEL) + EPSC);
                tension = (pn > 0.0f) ? (1.0f - overlap) : 1.0f;
            } else {
                const float xn = sqrtf((float)g_act_cntfull[t + 1]);
                tension = 1.0f - TD / (pn * xn + EPSC);
            }
            out[t] = tension;
        }
    }
}

// ---------------- launch ------------------------------------------------------
extern "C" void kernel_launch(void* const* d_in, const int* in_sizes, int n_in,
                              void* d_out, int out_size) {
    const int*   tokens = (const int*)d_in[0];
    const float* proj   = (const float*)d_in[1];
    const float* sigma  = (const float*)d_in[2];
    const int*   plast  = (const int*)d_in[3];
    float*       out    = (float*)d_out;

    k_prep<<<NTRB + TT, 256>>>(tokens, proj, sigma);
    k_match<<<TT - 1, 128>>>(plast);
    k_main<<<(TT - 1) * QSPL, 128>>>(plast, out);
}